// round 9
// baseline (speedup 1.0000x reference)
#include <cuda_runtime.h>
#include <cstdint>
#include <cstddef>

#define IMG_H 1024
#define IMG_W 1024
#define CHUNK 64             // output rows per warp (grid = 5*16*8 = 640 blocks, single wave)
#define USEFUL 56            // output cols per warp (local cols 4..59)
#define NSTRIPS 19           // ceil(1024 / 56)
#define WPB 4                // warps per block

__constant__ int c_dy[8] = {0, 1, 1, 1, 0, -1, -1, -1};
__constant__ int c_dx[8] = {1, 1, 0, -1, -1, -1, 0, 1};

// identical chain to the passing kernels — do not touch
__device__ __forceinline__ float blur5(float w0, float w1, float w2, float w3, float w4) {
    const float G0 = 0.13533528323661270f;   // exp(-2)
    const float G1 = 0.60653065971263342f;   // exp(-0.5)
    float a = __fmul_rn(G0, w0);
    a = __fmaf_rn(G1, w1, a);
    a = __fadd_rn(a, w2);
    a = __fmaf_rn(G1, w3, a);
    a = __fmaf_rn(G0, w4, a);
    return a;
}

// identical sobel chains — do not touch
__device__ __forceinline__ void sobel3(float L0, float C0, float R0,
                                       float L1, float R1,
                                       float L2, float C2, float R2,
                                       float& gxv, float& gyv) {
    gxv = L0;
    gxv = __fmaf_rn(-1.0f, R0, gxv);
    gxv = __fmaf_rn( 2.0f, L1, gxv);
    gxv = __fmaf_rn(-2.0f, R1, gxv);
    gxv = __fadd_rn(gxv, L2);
    gxv = __fmaf_rn(-1.0f, R2, gxv);
    gyv = L0;
    gyv = __fmaf_rn( 2.0f, C0, gyv);
    gyv = __fadd_rn(gyv, R0);
    gyv = __fmaf_rn(-1.0f, L2, gyv);
    gyv = __fmaf_rn(-2.0f, C2, gyv);
    gyv = __fmaf_rn(-1.0f, R2, gyv);
}

__device__ __forceinline__ float pick9(int dy, int dx,
                                       float tl, float tc, float tr,
                                       float cl, float cc, float cr,
                                       float bl, float bc, float br) {
    float rl, rc, rr;
    if (dy < 0)      { rl = tl; rc = tc; rr = tr; }
    else if (dy > 0) { rl = bl; rc = bc; rr = br; }
    else             { rl = cl; rc = cc; rr = cr; }
    return (dx < 0) ? rl : ((dx > 0) ? rr : rc);
}

// identical NMS/orientation sequence — do not touch
__device__ __forceinline__ float nms_px(float m, float gxd, float gyd,
                                        float tl, float tc, float tr,
                                        float cl, float cr,
                                        float bl, float bc, float br,
                                        int gy, int gx) {
    float ang = atan2f(gyd, gxd);
    float orient = __fadd_rn(__fmul_rn(ang, 57.295779513082323f), 180.0f);
    float o45 = __fdiv_rn(orient, 45.0f);
    int r = (int)rintf(o45);
    int ip = r & 7;
    int dy = c_dy[ip], dx = c_dx[ip];
    float posn = pick9( dy,  dx, tl, tc, tr, cl, m, cr, bl, bc, br);
    float negn = pick9(-dy, -dx, tl, tc, tr, cl, m, cr, bl, bc, br);
    float pos = __fadd_rn(m, -posn);
    float neg = __fadd_rn(m, -negn);
    float res = (fminf(pos, neg) > 0.0f && m >= 1.0f) ? m : 0.0f;
    if (gy == 0 || gy == IMG_H - 1 || gx == 0 || gx == IMG_W - 1)
        res = 0.0f;
    return res;
}

// MASKED=false: all rows/cols this warp touches (incl. one prefetch row) are
// in-bounds and colok holds for every lane — loads unpredicated, masks elided.
template<bool MASKED>
__device__ __forceinline__ void strip_body(
    const float* __restrict__ p0, const float* __restrict__ p1,
    const float* __restrict__ p2, float* __restrict__ po,
    int r0, int col0, int lane, bool colok)
{
    const unsigned FULL = 0xffffffffu;
    const float2 z = make_float2(0.f, 0.f);

    float2 hb[3][4];                  // hblur rows ri-4..ri-1
    float2 vbw[3][2];                 // blurred rows ri-4, ri-3 (own 2 cols)
    float  vL[3][2], vR[3][2];        // blurred left/right neighbor cols
    #pragma unroll
    for (int c = 0; c < 3; c++) {
        #pragma unroll
        for (int j = 0; j < 4; j++) hb[c][j] = z;
        #pragma unroll
        for (int j = 0; j < 2; j++) { vbw[c][j] = z; vL[c][j] = 0.f; vR[c][j] = 0.f; }
    }
    float2 mg0 = z, mg1 = z;
    float  mgL0 = 0.f, mgL1 = 0.f, mgR0 = 0.f, mgR1 = 0.f;
    float2 gxd = z, gyd = z;

    // preload input row r0-4
    const ptrdiff_t roff = (ptrdiff_t)(r0 - 4) * IMG_W;
    float2 xc0 = z, xc1 = z, xc2 = z;
    if (!MASKED || ((unsigned)(r0 - 4) < (unsigned)IMG_H && colok)) {
        xc0 = __ldg((const float2*)(p0 + roff));
        xc1 = __ldg((const float2*)(p1 + roff));
        xc2 = __ldg((const float2*)(p2 + roff));
    }
    const float* q0 = p0 + roff + IMG_W;
    const float* q1 = p1 + roff + IMG_W;
    const float* q2 = p2 + roff + IMG_W;
    float* prow = po + (size_t)r0 * IMG_W + col0;

    #pragma unroll 4
    for (int it = 0; it < CHUNK + 8; it++) {
        const int ri = r0 - 4 + it;

        // prefetch next input row (fast path: always in-bounds by dispatch)
        float2 xn0 = z, xn1 = z, xn2 = z;
        if (!MASKED || ((unsigned)(ri + 1) < (unsigned)IMG_H && colok)) {
            xn0 = __ldg((const float2*)q0);
            xn1 = __ldg((const float2*)q1);
            xn2 = __ldg((const float2*)q2);
        }
        q0 += IMG_W; q1 += IMG_W; q2 += IMG_W;

        const bool vrowok = !MASKED || (unsigned)(ri - 2) < (unsigned)IMG_H;
        const bool srowok = !MASKED || (unsigned)(ri - 3) < (unsigned)IMG_H;

        float2 mag_new = z, gxs = z, gys = z;
        float2 xin[3] = {xc0, xc1, xc2};
        #pragma unroll
        for (int c = 0; c < 3; c++) {
            float2 x = xin[c];
            float pl_lo = __shfl_up_sync  (FULL, x.x, 1);  // col0-2
            float pl_hi = __shfl_up_sync  (FULL, x.y, 1);  // col0-1
            float nx_lo = __shfl_down_sync(FULL, x.x, 1);  // col0+2
            float nx_hi = __shfl_down_sync(FULL, x.y, 1);  // col0+3
            float hb_lo = blur5(pl_lo, pl_hi, x.x, x.y, nx_lo);
            float hb_hi = blur5(pl_hi, x.x, x.y, nx_lo, nx_hi);

            float vb_lo = blur5(hb[c][0].x, hb[c][1].x, hb[c][2].x, hb[c][3].x, hb_lo);
            float vb_hi = blur5(hb[c][0].y, hb[c][1].y, hb[c][2].y, hb[c][3].y, hb_hi);
            if (MASKED && (!colok || !vrowok)) { vb_lo = 0.f; vb_hi = 0.f; }
            hb[c][0] = hb[c][1]; hb[c][1] = hb[c][2];
            hb[c][2] = hb[c][3]; hb[c][3] = make_float2(hb_lo, hb_hi);

            float vLn = __shfl_up_sync  (FULL, vb_hi, 1);  // col0-1
            float vRn = __shfl_down_sync(FULL, vb_lo, 1);  // col0+2

            float gx_lo, gy_lo, gx_hi, gy_hi;
            sobel3(vL[c][0],    vbw[c][0].x, vbw[c][0].y,
                   vL[c][1],                 vbw[c][1].y,
                   vLn,         vb_lo,       vb_hi,       gx_lo, gy_lo);
            sobel3(vbw[c][0].x, vbw[c][0].y, vR[c][0],
                   vbw[c][1].x,              vR[c][1],
                   vb_lo,       vb_hi,       vRn,         gx_hi, gy_hi);

            float s_lo = __fadd_rn(__fmul_rn(gx_lo, gx_lo), __fmul_rn(gy_lo, gy_lo));
            s_lo = __fadd_rn(s_lo, 1e-8f);
            float m_lo = __fsqrt_rn(s_lo);
            float s_hi = __fadd_rn(__fmul_rn(gx_hi, gx_hi), __fmul_rn(gy_hi, gy_hi));
            s_hi = __fadd_rn(s_hi, 1e-8f);
            float m_hi = __fsqrt_rn(s_hi);
            if (MASKED && (!srowok || !colok)) { m_lo = 0.f; m_hi = 0.f; }

            if (c == 0) {
                mag_new = make_float2(m_lo, m_hi);
                gxs = make_float2(gx_lo, gx_hi);
                gys = make_float2(gy_lo, gy_hi);
            } else {
                mag_new.x = __fadd_rn(mag_new.x, m_lo);
                mag_new.y = __fadd_rn(mag_new.y, m_hi);
                gxs.x = __fadd_rn(gxs.x, gx_lo);
                gxs.y = __fadd_rn(gxs.y, gx_hi);
                gys.x = __fadd_rn(gys.x, gy_lo);
                gys.y = __fadd_rn(gys.y, gy_hi);
            }

            vbw[c][0] = vbw[c][1]; vbw[c][1] = make_float2(vb_lo, vb_hi);
            vL[c][0] = vL[c][1];   vL[c][1] = vLn;
            vR[c][0] = vR[c][1];   vR[c][1] = vRn;
        }

        float mgLn = __shfl_up_sync  (FULL, mag_new.y, 1);  // col0-1
        float mgRn = __shfl_down_sync(FULL, mag_new.x, 1);  // col0+2

        // output row ro = ri-4 (mag rows ro-1, ro, ro+1 = mg0, mg1, mag_new)
        const int ro = ri - 4;
        if (ro >= r0) {
            if (lane >= 2 && lane <= 29 && (!MASKED || colok)) {
                float res_lo = nms_px(mg1.x, gxd.x, gyd.x,
                                      mgL0, mg0.x, mg0.y,
                                      mgL1,        mg1.y,
                                      mgLn, mag_new.x, mag_new.y,
                                      ro, col0);
                float res_hi = nms_px(mg1.y, gxd.y, gyd.y,
                                      mg0.x, mg0.y, mgR0,
                                      mg1.x,        mgR1,
                                      mag_new.x, mag_new.y, mgRn,
                                      ro, col0 + 1);
                *(float2*)prow = make_float2(res_lo, res_hi);
            }
            prow += IMG_W;
        }

        mg0 = mg1; mg1 = mag_new;
        mgL0 = mgL1; mgL1 = mgLn;
        mgR0 = mgR1; mgR1 = mgRn;
        gxd = gxs; gyd = gys;
        xc0 = xn0; xc1 = xn1; xc2 = xn2;
    }
}

__global__ __launch_bounds__(128, 5)
void canny_sliding4(const float* __restrict__ img, float* __restrict__ out) {
    const int lane  = threadIdx.x & 31;
    const int warp  = threadIdx.x >> 5;
    const int strip = blockIdx.x * WPB + warp;
    if (strip >= NSTRIPS) return;

    const int b    = blockIdx.z;
    const int r0   = blockIdx.y * CHUNK;
    const int col0 = strip * USEFUL - 4 + 2 * lane;       // even; lane owns col0, col0+1
    const bool colok = (unsigned)col0 < (unsigned)IMG_W;

    const float* p0 = img + ((size_t)(b * 3 + 0) << 20) + col0;
    const float* p1 = img + ((size_t)(b * 3 + 1) << 20) + col0;
    const float* p2 = img + ((size_t)(b * 3 + 2) << 20) + col0;
    float* po = out + ((size_t)b << 20);

    // fast iff every touched row (incl. final prefetch r0+CHUNK+4) and every
    // lane's column pair are strictly in-bounds
    const bool fast = (r0 >= 4) && (r0 + CHUNK + 4 <= IMG_H - 1) &&
                      (strip >= 1) && (strip * USEFUL + 58 <= IMG_W - 1);

    if (fast) strip_body<false>(p0, p1, p2, po, r0, col0, lane, colok);
    else      strip_body<true >(p0, p1, p2, po, r0, col0, lane, colok);
}

extern "C" void kernel_launch(void* const* d_in, const int* in_sizes, int n_in,
                              void* d_out, int out_size) {
    const float* img = (const float*)d_in[0];
    float* o = (float*)d_out;
    dim3 grid((NSTRIPS + WPB - 1) / WPB, IMG_H / CHUNK, 8);
    canny_sliding4<<<grid, WPB * 32>>>(img, o);
}

// round 11
// speedup vs baseline: 1.2695x; 1.2695x over previous
#include <cuda_runtime.h>
#include <cstdint>

#define IMG_H 1024
#define IMG_W 1024
#define CHUNK 64             // output rows per warp (grid = 11*16*8 = 1408 blocks, all resident)
#define USEFUL 24            // output cols per warp (lanes 4..27)
#define NSTRIPS 43           // ceil(1024 / 24)
#define WPB 4                // warps per block

__constant__ int c_dy[8] = {0, 1, 1, 1, 0, -1, -1, -1};
__constant__ int c_dx[8] = {1, 1, 0, -1, -1, -1, 0, 1};

// identical chain to the passing R4 kernel — do not touch
__device__ __forceinline__ float blur5(float w0, float w1, float w2, float w3, float w4) {
    const float G0 = 0.13533528323661270f;   // exp(-2)
    const float G1 = 0.60653065971263342f;   // exp(-0.5)
    float a = __fmul_rn(G0, w0);
    a = __fmaf_rn(G1, w1, a);
    a = __fadd_rn(a, w2);
    a = __fmaf_rn(G1, w3, a);
    a = __fmaf_rn(G0, w4, a);
    return a;
}

// select mag neighbor at (row dy, col dx) from the 3x3 register window
__device__ __forceinline__ float pick9(int dy, int dx,
                                       float tl, float tc, float tr,
                                       float cl, float cc, float cr,
                                       float bl, float bc, float br) {
    float rl, rc, rr;
    if (dy < 0)      { rl = tl; rc = tc; rr = tr; }
    else if (dy > 0) { rl = bl; rc = bc; rr = br; }
    else             { rl = cl; rc = cc; rr = cr; }
    return (dx < 0) ? rl : ((dx > 0) ? rr : rc);
}

__global__ __launch_bounds__(128, 5)
void canny_sliding(const float* __restrict__ img, float* __restrict__ out) {
    const unsigned FULL = 0xffffffffu;
    const int lane  = threadIdx.x & 31;
    const int warp  = threadIdx.x >> 5;
    const int strip = blockIdx.x * WPB + warp;
    if (strip >= NSTRIPS) return;

    const int b   = blockIdx.z;
    const int r0  = blockIdx.y * CHUNK;
    const int col = strip * USEFUL + lane - 4;            // may be <0 or >=W in halo lanes
    const bool colok = (unsigned)col < (unsigned)IMG_W;

    const float* p0 = img + ((size_t)(b * 3 + 0) << 20) + col;
    const float* p1 = img + ((size_t)(b * 3 + 1) << 20) + col;
    const float* p2 = img + ((size_t)(b * 3 + 2) << 20) + col;
    float* po = out + ((size_t)b << 20);

    // register pipeline state (all zero-init; garbage rows never consumed)
    float hb[3][4];              // hblur rows ri-4..ri-1
    float vl[3][2], vc[3][2], vr[3][2];  // blurred (L/C/R) rows ri-4, ri-3
    #pragma unroll
    for (int c = 0; c < 3; c++) {
        hb[c][0] = hb[c][1] = hb[c][2] = hb[c][3] = 0.0f;
        vl[c][0] = vl[c][1] = 0.0f;
        vc[c][0] = vc[c][1] = 0.0f;
        vr[c][0] = vr[c][1] = 0.0f;
    }
    float mg_m2 = 0.0f, mg_m1 = 0.0f;    // mag rows ri-5, ri-4
    float ml_m2 = 0.0f, ml_m1 = 0.0f;
    float mr_m2 = 0.0f, mr_m1 = 0.0f;
    float gxs_d = 0.0f, gys_d = 0.0f;    // gx/gy sums at row ri-4

    // preload input row r0-4
    float xc0, xc1, xc2;
    {
        int ri = r0 - 4;
        bool rowok = (unsigned)ri < (unsigned)IMG_H;
        size_t off = (size_t)ri * IMG_W;
        xc0 = (rowok && colok) ? __ldg(p0 + off) : 0.0f;
        xc1 = (rowok && colok) ? __ldg(p1 + off) : 0.0f;
        xc2 = (rowok && colok) ? __ldg(p2 + off) : 0.0f;
    }

    #pragma unroll 2
    for (int ri = r0 - 4; ri <= r0 + CHUNK + 3; ri++) {
        // prefetch next input row (off critical path)
        float xn0 = 0.0f, xn1 = 0.0f, xn2 = 0.0f;
        {
            int rn2 = ri + 1;
            bool rowok = (unsigned)rn2 < (unsigned)IMG_H;
            if (rowok && colok) {
                size_t off = (size_t)rn2 * IMG_W;
                xn0 = __ldg(p0 + off);
                xn1 = __ldg(p1 + off);
                xn2 = __ldg(p2 + off);
            }
        }

        const bool vrowok = (unsigned)(ri - 2) < (unsigned)IMG_H;  // blurred row
        const bool srowok = (unsigned)(ri - 3) < (unsigned)IMG_H;  // sobel/mag row

        float mag_new = 0.0f, gxs = 0.0f, gys = 0.0f;
        float xin[3] = {xc0, xc1, xc2};
        #pragma unroll
        for (int c = 0; c < 3; c++) {
            float x = xin[c];
            // horizontal 5-tap via shuffles (halo lanes produce unused garbage)
            float xm2 = __shfl_up_sync  (FULL, x, 2);
            float xm1 = __shfl_up_sync  (FULL, x, 1);
            float xp1 = __shfl_down_sync(FULL, x, 1);
            float xp2 = __shfl_down_sync(FULL, x, 2);
            float hbn = blur5(xm2, xm1, x, xp1, xp2);

            // vertical 5-tap for blurred row ri-2; mask to zero outside image
            float vbn = blur5(hb[c][0], hb[c][1], hb[c][2], hb[c][3], hbn);
            if (!colok || !vrowok) vbn = 0.0f;
            hb[c][0] = hb[c][1]; hb[c][1] = hb[c][2];
            hb[c][2] = hb[c][3]; hb[c][3] = hbn;

            float vln = __shfl_up_sync  (FULL, vbn, 1);
            float vrn = __shfl_down_sync(FULL, vbn, 1);

            // sobel at row ri-3: rows (ri-4, ri-3, ri-2) = (idx0, idx1, new)
            float L0 = vl[c][0], C0 = vc[c][0], R0 = vr[c][0];
            float L1 = vl[c][1],                R1 = vr[c][1];
            float L2 = vln,      C2 = vbn,      R2 = vrn;
            float gxv = L0;
            gxv = __fmaf_rn(-1.0f, R0, gxv);
            gxv = __fmaf_rn( 2.0f, L1, gxv);
            gxv = __fmaf_rn(-2.0f, R1, gxv);
            gxv = __fadd_rn(gxv, L2);
            gxv = __fmaf_rn(-1.0f, R2, gxv);
            float gyv = L0;
            gyv = __fmaf_rn( 2.0f, C0, gyv);
            gyv = __fadd_rn(gyv, R0);
            gyv = __fmaf_rn(-1.0f, L2, gyv);
            gyv = __fmaf_rn(-2.0f, C2, gyv);
            gyv = __fmaf_rn(-1.0f, R2, gyv);
            float s = __fadd_rn(__fmul_rn(gxv, gxv), __fmul_rn(gyv, gyv));
            s = __fadd_rn(s, 1e-8f);
            float m = __fsqrt_rn(s);
            if (!srowok || !colok) m = 0.0f;

            // channel accumulation, same order/rounding as before
            if (c == 0) { mag_new = m; gxs = gxv; gys = gyv; }
            else {
                mag_new = __fadd_rn(mag_new, m);
                gxs = __fadd_rn(gxs, gxv);
                gys = __fadd_rn(gys, gyv);
            }

            vl[c][0] = vl[c][1]; vl[c][1] = vln;
            vc[c][0] = vc[c][1]; vc[c][1] = vbn;
            vr[c][0] = vr[c][1]; vr[c][1] = vrn;
        }

        float mln = __shfl_up_sync  (FULL, mag_new, 1);
        float mrn = __shfl_down_sync(FULL, mag_new, 1);

        // output row ro = ri-4: mag rows (ro-1, ro, ro+1) = (_m2, _m1, new)
        int ro = ri - 4;
        if (ro >= r0 && lane >= 4 && lane <= 27 && colok) {
            float m = mg_m1;
            float ang = atan2f(gys_d, gxs_d);
            float orient = __fadd_rn(__fmul_rn(ang, 57.295779513082323f), 180.0f);
            float o45 = __fdiv_rn(orient, 45.0f);
            int r = (int)rintf(o45);
            int ip = r & 7;
            int dy = c_dy[ip], dx = c_dx[ip];
            float posn = pick9( dy,  dx, ml_m2, mg_m2, mr_m2,
                                         ml_m1, mg_m1, mr_m1,
                                         mln,   mag_new, mrn);
            float negn = pick9(-dy, -dx, ml_m2, mg_m2, mr_m2,
                                         ml_m1, mg_m1, mr_m1,
                                         mln,   mag_new, mrn);
            float pos = __fadd_rn(m, -posn);
            float neg = __fadd_rn(m, -negn);
            float res = (fminf(pos, neg) > 0.0f && m >= 1.0f) ? m : 0.0f;
            if (ro == 0 || ro == IMG_H - 1 || col == 0 || col == IMG_W - 1)
                res = 0.0f;
            po[(size_t)ro * IMG_W + col] = res;
        }

        // slide windows
        mg_m2 = mg_m1; mg_m1 = mag_new;
        ml_m2 = ml_m1; ml_m1 = mln;
        mr_m2 = mr_m1; mr_m1 = mrn;
        gxs_d = gxs;   gys_d = gys;
        xc0 = xn0; xc1 = xn1; xc2 = xn2;
    }
}

extern "C" void kernel_launch(void* const* d_in, const int* in_sizes, int n_in,
                              void* d_out, int out_size) {
    const float* img = (const float*)d_in[0];
    float* o = (float*)d_out;
    dim3 grid((NSTRIPS + WPB - 1) / WPB, IMG_H / CHUNK, 8);
    canny_sliding<<<grid, WPB * 32>>>(img, o);
}

// round 12
// speedup vs baseline: 1.3553x; 1.0675x over previous
#include <cuda_runtime.h>
#include <cstdint>

#define IMG_H 1024
#define IMG_W 1024
#define CHUNK 64             // output rows per warp (grid = 11*16*8 = 1408 blocks)
#define USEFUL 24            // output cols per warp (lanes 4..27)
#define NSTRIPS 43           // ceil(1024 / 24)
#define WPB 4                // warps per block

__constant__ int c_dy[8] = {0, 1, 1, 1, 0, -1, -1, -1};
__constant__ int c_dx[8] = {1, 1, 0, -1, -1, -1, 0, 1};

// identical chain to the passing kernels — do not touch
__device__ __forceinline__ float blur5(float w0, float w1, float w2, float w3, float w4) {
    const float G0 = 0.13533528323661270f;   // exp(-2)
    const float G1 = 0.60653065971263342f;   // exp(-0.5)
    float a = __fmul_rn(G0, w0);
    a = __fmaf_rn(G1, w1, a);
    a = __fadd_rn(a, w2);
    a = __fmaf_rn(G1, w3, a);
    a = __fmaf_rn(G0, w4, a);
    return a;
}

// select mag neighbor at (row dy, col dx) from the 3x3 register window
__device__ __forceinline__ float pick9(int dy, int dx,
                                       float tl, float tc, float tr,
                                       float cl, float cc, float cr,
                                       float bl, float bc, float br) {
    float rl, rc, rr;
    if (dy < 0)      { rl = tl; rc = tc; rr = tr; }
    else if (dy > 0) { rl = bl; rc = bc; rr = br; }
    else             { rl = cl; rc = cc; rr = cr; }
    return (dx < 0) ? rl : ((dx > 0) ? rr : rc);
}

__global__ __launch_bounds__(128, 5)
void canny_sliding(const float* __restrict__ img, float* __restrict__ out) {
    const unsigned FULL = 0xffffffffu;
    const int lane  = threadIdx.x & 31;
    const int warp  = threadIdx.x >> 5;
    const int strip = blockIdx.x * WPB + warp;
    if (strip >= NSTRIPS) return;

    const int b   = blockIdx.z;
    const int r0  = blockIdx.y * CHUNK;
    const int col = strip * USEFUL + lane - 4;            // may be <0 or >=W in halo lanes
    const bool colok = (unsigned)col < (unsigned)IMG_W;

    const float* p0 = img + ((size_t)(b * 3 + 0) << 20) + col;
    const float* p1 = img + ((size_t)(b * 3 + 1) << 20) + col;
    const float* p2 = img + ((size_t)(b * 3 + 2) << 20) + col;
    float* po = out + ((size_t)b << 20);

    // register pipeline state (all zero-init; garbage rows never consumed)
    float hb[3][4];              // hblur rows ri-4..ri-1
    float vl[3][2], vc[3][2], vr[3][2];  // blurred (L/C/R) rows ri-4, ri-3
    #pragma unroll
    for (int c = 0; c < 3; c++) {
        hb[c][0] = hb[c][1] = hb[c][2] = hb[c][3] = 0.0f;
        vl[c][0] = vl[c][1] = 0.0f;
        vc[c][0] = vc[c][1] = 0.0f;
        vr[c][0] = vr[c][1] = 0.0f;
    }
    float mg_m2 = 0.0f, mg_m1 = 0.0f;    // mag rows ri-5, ri-4
    float ml_m2 = 0.0f, ml_m1 = 0.0f;
    float mr_m2 = 0.0f, mr_m1 = 0.0f;
    float gxs_d = 0.0f, gys_d = 0.0f;    // gx/gy sums at row ri-4

    // preload input row r0-4
    float xc0, xc1, xc2;
    {
        int ri = r0 - 4;
        bool rowok = (unsigned)ri < (unsigned)IMG_H;
        size_t off = (size_t)ri * IMG_W;
        xc0 = (rowok && colok) ? __ldg(p0 + off) : 0.0f;
        xc1 = (rowok && colok) ? __ldg(p1 + off) : 0.0f;
        xc2 = (rowok && colok) ? __ldg(p2 + off) : 0.0f;
    }

    #pragma unroll 4
    for (int ri = r0 - 4; ri <= r0 + CHUNK + 3; ri++) {
        // prefetch next input row (off critical path)
        float xn0 = 0.0f, xn1 = 0.0f, xn2 = 0.0f;
        {
            int rn2 = ri + 1;
            bool rowok = (unsigned)rn2 < (unsigned)IMG_H;
            if (rowok && colok) {
                size_t off = (size_t)rn2 * IMG_W;
                xn0 = __ldg(p0 + off);
                xn1 = __ldg(p1 + off);
                xn2 = __ldg(p2 + off);
            }
        }

        const bool vrowok = (unsigned)(ri - 2) < (unsigned)IMG_H;  // blurred row
        const bool srowok = (unsigned)(ri - 3) < (unsigned)IMG_H;  // sobel/mag row

        float mag_new = 0.0f, gxs = 0.0f, gys = 0.0f;
        float xin[3] = {xc0, xc1, xc2};
        #pragma unroll
        for (int c = 0; c < 3; c++) {
            float x = xin[c];
            // horizontal 5-tap via shuffles (halo lanes produce unused garbage)
            float xm2 = __shfl_up_sync  (FULL, x, 2);
            float xm1 = __shfl_up_sync  (FULL, x, 1);
            float xp1 = __shfl_down_sync(FULL, x, 1);
            float xp2 = __shfl_down_sync(FULL, x, 2);
            float hbn = blur5(xm2, xm1, x, xp1, xp2);

            // vertical 5-tap for blurred row ri-2; mask to zero outside image
            float vbn = blur5(hb[c][0], hb[c][1], hb[c][2], hb[c][3], hbn);
            if (!colok || !vrowok) vbn = 0.0f;
            hb[c][0] = hb[c][1]; hb[c][1] = hb[c][2];
            hb[c][2] = hb[c][3]; hb[c][3] = hbn;

            float vln = __shfl_up_sync  (FULL, vbn, 1);
            float vrn = __shfl_down_sync(FULL, vbn, 1);

            // sobel at row ri-3: rows (ri-4, ri-3, ri-2) = (idx0, idx1, new)
            float L0 = vl[c][0], C0 = vc[c][0], R0 = vr[c][0];
            float L1 = vl[c][1],                R1 = vr[c][1];
            float L2 = vln,      C2 = vbn,      R2 = vrn;
            float gxv = L0;
            gxv = __fmaf_rn(-1.0f, R0, gxv);
            gxv = __fmaf_rn( 2.0f, L1, gxv);
            gxv = __fmaf_rn(-2.0f, R1, gxv);
            gxv = __fadd_rn(gxv, L2);
            gxv = __fmaf_rn(-1.0f, R2, gxv);
            float gyv = L0;
            gyv = __fmaf_rn( 2.0f, C0, gyv);
            gyv = __fadd_rn(gyv, R0);
            gyv = __fmaf_rn(-1.0f, L2, gyv);
            gyv = __fmaf_rn(-2.0f, C2, gyv);
            gyv = __fmaf_rn(-1.0f, R2, gyv);
            float s = __fadd_rn(__fmul_rn(gxv, gxv), __fmul_rn(gyv, gyv));
            s = __fadd_rn(s, 1e-8f);
            float m = __fsqrt_rn(s);
            if (!srowok || !colok) m = 0.0f;

            // channel accumulation, same order/rounding as before
            if (c == 0) { mag_new = m; gxs = gxv; gys = gyv; }
            else {
                mag_new = __fadd_rn(mag_new, m);
                gxs = __fadd_rn(gxs, gxv);
                gys = __fadd_rn(gys, gyv);
            }

            vl[c][0] = vl[c][1]; vl[c][1] = vln;
            vc[c][0] = vc[c][1]; vc[c][1] = vbn;
            vr[c][0] = vr[c][1]; vr[c][1] = vrn;
        }

        float mln = __shfl_up_sync  (FULL, mag_new, 1);
        float mrn = __shfl_down_sync(FULL, mag_new, 1);

        // output row ro = ri-4: mag rows (ro-1, ro, ro+1) = (_m2, _m1, new)
        int ro = ri - 4;
        if (ro >= r0 && lane >= 4 && lane <= 27 && colok) {
            float m = mg_m1;
            float ang = atan2f(gys_d, gxs_d);
            float orient = __fadd_rn(__fmul_rn(ang, 57.295779513082323f), 180.0f);
            float o45 = __fdiv_rn(orient, 45.0f);
            int r = (int)rintf(o45);
            int ip = r & 7;
            int dy = c_dy[ip], dx = c_dx[ip];
            float posn = pick9( dy,  dx, ml_m2, mg_m2, mr_m2,
                                         ml_m1, mg_m1, mr_m1,
                                         mln,   mag_new, mrn);
            float negn = pick9(-dy, -dx, ml_m2, mg_m2, mr_m2,
                                         ml_m1, mg_m1, mr_m1,
                                         mln,   mag_new, mrn);
            float pos = __fadd_rn(m, -posn);
            float neg = __fadd_rn(m, -negn);
            float res = (fminf(pos, neg) > 0.0f && m >= 1.0f) ? m : 0.0f;
            if (ro == 0 || ro == IMG_H - 1 || col == 0 || col == IMG_W - 1)
                res = 0.0f;
            po[(size_t)ro * IMG_W + col] = res;
        }

        // slide windows
        mg_m2 = mg_m1; mg_m1 = mag_new;
        ml_m2 = ml_m1; ml_m1 = mln;
        mr_m2 = mr_m1; mr_m1 = mrn;
        gxs_d = gxs;   gys_d = gys;
        xc0 = xn0; xc1 = xn1; xc2 = xn2;
    }
}

extern "C" void kernel_launch(void* const* d_in, const int* in_sizes, int n_in,
                              void* d_out, int out_size) {
    const float* img = (const float*)d_in[0];
    float* o = (float*)d_out;
    dim3 grid((NSTRIPS + WPB - 1) / WPB, IMG_H / CHUNK, 8);
    canny_sliding<<<grid, WPB * 32>>>(img, o);
}